// round 4
// baseline (speedup 1.0000x reference)
#include <cuda_runtime.h>

#define DT    0.04f
#define DT2   (0.04f * 0.04f * 0.5f)
#define AXM   9.0f
#define PDM   1.244f
#define SPM   20.0f

#define BLK     128      // threads per block = trajectories per block
#define TCHUNK  8        // time steps per tile
#define NTILE   (128 / TCHUNK)          // 16 tiles
#define IN_F4   (TCHUNK * 2 / 4)        // float4 of motion per traj per tile = 4
#define OUT_F4  (TCHUNK)                // float4 of output per traj per tile = 8
#define IN_PITCH  5                     // pad 4 -> 5 (conflict-free compute LDS)
#define OUT_PITCH 9                     // pad 8 -> 9 (conflict-free STS/LDS)

__device__ __forceinline__ void step(float& x, float& y, float& v, float& psi,
                                     float m0, float m1) {
    float ax = fminf(fmaxf(m0, -AXM), AXM);
    float pd = fminf(fmaxf(m1, -PDM), PDM);
    float sn, cs;
    __sincosf(psi, &sn, &cs);
    x = fmaf(v * cs, DT, fmaf(fmaf(ax, cs, -pd * v * sn), DT2, x));
    y = fmaf(v * sn, DT, fmaf(fmaf(ax, sn,  pd * v * cs), DT2, y));
    v = fminf(fmaxf(fmaf(ax, DT, v), -SPM), SPM);
    psi = fmaf(pd, DT, psi);
}

__global__ __launch_bounds__(BLK)
void kin_kernel(const float4* __restrict__ motion,   // [B,128,2] = 64 float4 / traj
                const float4* __restrict__ init,     // [B,4]     = 1 float4 / traj
                float4* __restrict__ out)            // [B,128,4] = 128 float4 / traj
{
    __shared__ float4 s_in [BLK][IN_PITCH];    // 10 KiB
    __shared__ float4 s_out[BLK][OUT_PITCH];   // 18 KiB

    const int tid = threadIdx.x;
    const int b0  = blockIdx.x * BLK;

    // per-thread staging assignment (fixed across tiles)
    const int in_row = tid >> 2, in_col = tid & 3;   // with k offset below

    float4 s = init[b0 + tid];
    float x = s.x, y = s.y, v = s.z, psi = s.w;

    // ---- preload tile 0 motion into registers (coalesced LDG.128) ----
    float4 r_in[IN_F4];
    #pragma unroll
    for (int k = 0; k < IN_F4; k++) {
        int idx = k * BLK + tid;
        int row = idx >> 2, col = idx & 3;
        r_in[k] = motion[(size_t)(b0 + row) * 64 + col];
    }

    #pragma unroll 1
    for (int tile = 0; tile < NTILE; tile++) {
        // ---- commit staged registers to smem ----
        #pragma unroll
        for (int k = 0; k < IN_F4; k++) {
            int idx = k * BLK + tid;
            int row = idx >> 2, col = idx & 3;
            s_in[row][col] = r_in[k];
        }
        __syncthreads();

        // ---- issue next tile's LDGs NOW (overlap with compute) ----
        if (tile + 1 < NTILE) {
            #pragma unroll
            for (int k = 0; k < IN_F4; k++) {
                int idx = k * BLK + tid;
                int row = idx >> 2, col = idx & 3;
                r_in[k] = motion[(size_t)(b0 + row) * 64 + (tile + 1) * IN_F4 + col];
            }
        }

        // ---- compute 8 steps from own smem row, stage results ----
        #pragma unroll
        for (int j = 0; j < IN_F4; j++) {
            float4 mp = s_in[tid][j];    // steps 2j, 2j+1
            step(x, y, v, psi, mp.x, mp.y);
            s_out[tid][2 * j]     = make_float4(x, y, v, psi);
            step(x, y, v, psi, mp.z, mp.w);
            s_out[tid][2 * j + 1] = make_float4(x, y, v, psi);
        }
        __syncthreads();

        // ---- drain output tile: coalesced STG (full 128B line per traj) ----
        #pragma unroll
        for (int k = 0; k < OUT_F4; k++) {
            int idx = k * BLK + tid;
            int row = idx >> 3, col = idx & 7;
            out[(size_t)(b0 + row) * 128 + tile * OUT_F4 + col] = s_out[row][col];
        }
        __syncthreads();   // protect s_in (rewritten next iter) & s_out
    }
}

extern "C" void kernel_launch(void* const* d_in, const int* in_sizes, int n_in,
                              void* d_out, int out_size) {
    const float4* motion = (const float4*)d_in[0];  // motion_params [B,128,2] f32
    const float4* init   = (const float4*)d_in[1];  // init_state   [B,4]     f32
    float4*       out    = (float4*)d_out;          // [B,128,4] f32

    int B = in_sizes[1] / 4;                        // 262144
    int blocks = B / BLK;                           // 2048
    kin_kernel<<<blocks, BLK>>>(motion, init, out);
}